// round 5
// baseline (speedup 1.0000x reference)
#include <cuda_runtime.h>
#include <cstdint>

#define NF     16
#define EMBED  256
#define BATCH  2048
#define NPAIR  120

#define BM 128
#define BN 128
#define BK 32
#define NCHUNK (EMBED / BK)   // 8
#define THREADS 256

#define TILE_BYTES (128 * BK * 4)   // 16384
#define OFF_A0 0
#define OFF_B0 32768
#define SMEM_TOTAL 65536

// static scratch (allocation-free rule)
__device__ float g_Wt[(size_t)NPAIR * EMBED * EMBED];   // W^T per pair: [p][f][e], tf32-rounded
__device__ float g_embr[(size_t)BATCH * NF * EMBED];    // emb, tf32-rounded

// ---------------- helpers ----------------
__device__ __forceinline__ uint32_t smem_u32(const void* p) {
    return (uint32_t)__cvta_generic_to_shared(p);
}
__device__ __forceinline__ void cp_async16(uint32_t dst, const void* src) {
    asm volatile("cp.async.cg.shared.global [%0], [%1], 16;\n" :: "r"(dst), "l"(src));
}
__device__ __forceinline__ void cp_commit() {
    asm volatile("cp.async.commit_group;\n" ::: "memory");
}
__device__ __forceinline__ float tf32r(float f) {
    uint32_t r;
    asm("cvt.rna.tf32.f32 %0, %1;" : "=r"(r) : "f"(f));
    return __uint_as_float(r);
}
#define SWZ(x) ((x) ^ (((x) >> 3) & 0x70))

__device__ __forceinline__ void ldm_x4(uint32_t* r, uint32_t addr) {
    asm volatile(
        "ldmatrix.sync.aligned.m8n8.x4.shared.b16 {%0,%1,%2,%3}, [%4];"
        : "=r"(r[0]), "=r"(r[1]), "=r"(r[2]), "=r"(r[3]) : "r"(addr));
}
__device__ __forceinline__ void mma_tf32(float c[4], const uint32_t a[4],
                                         uint32_t b0, uint32_t b1) {
    asm volatile(
        "mma.sync.aligned.m16n8k8.row.col.f32.tf32.tf32.f32 "
        "{%0,%1,%2,%3}, {%4,%5,%6,%7}, {%8,%9}, {%0,%1,%2,%3};\n"
        : "+f"(c[0]), "+f"(c[1]), "+f"(c[2]), "+f"(c[3])
        : "r"(a[0]), "r"(a[1]), "r"(a[2]), "r"(a[3]), "r"(b0), "r"(b1));
}

// ---------------- prep kernels ----------------
// Transpose + tf32-round W:  g_Wt[p][f][e] = rna(W[p][e][f])
__global__ void prep_weight(const float* __restrict__ w) {
    __shared__ float t[32][33];
    const int p  = blockIdx.z;
    const int f0 = blockIdx.x * 32;
    const int e0 = blockIdx.y * 32;
    const int tx = threadIdx.x, ty = threadIdx.y;   // 32 x 8
    const float* W = w + (size_t)p * EMBED * EMBED;
    #pragma unroll
    for (int r = 0; r < 4; ++r)
        t[ty + 8 * r][tx] = W[(size_t)(e0 + ty + 8 * r) * EMBED + f0 + tx];
    __syncthreads();
    float* Wt = g_Wt + (size_t)p * EMBED * EMBED;
    #pragma unroll
    for (int r = 0; r < 4; ++r)
        Wt[(size_t)(f0 + ty + 8 * r) * EMBED + e0 + tx] = tf32r(t[tx][ty + 8 * r]);
}

// tf32-round emb into g_embr
__global__ void prep_emb(const float4* __restrict__ e) {
    const int idx = blockIdx.x * blockDim.x + threadIdx.x;   // 2,097,152 float4
    float4 v = e[idx];
    v.x = tf32r(v.x); v.y = tf32r(v.y); v.z = tf32r(v.z); v.w = tf32r(v.w);
    reinterpret_cast<float4*>(g_embr)[idx] = v;
}

// ---------------- main kernel ----------------
__global__ void __launch_bounds__(THREADS, 2)
bilinear_mma(const float* __restrict__ emb,
             const float* __restrict__ bias,
             float* __restrict__ out)
{
    extern __shared__ __align__(1024) char smem[];
    const uint32_t sb = smem_u32(smem);

    const int tid  = threadIdx.x;
    const int lane = tid & 31;
    const int warp = tid >> 5;
    const int wm   = warp & 1;    // 64-row slab
    const int wn   = warp >> 1;   // 32-col slab

    const int bm0 = blockIdx.x * BM;
    const int bn0 = blockIdx.y * BN;
    const int p   = blockIdx.z;

    // pair p -> (i, j) of triu_indices(16, k=1)
    int i = 0, rem = p;
    while (rem >= (NF - 1) - i) { rem -= (NF - 1) - i; ++i; }
    const int j = i + 1 + rem;

    const float* Ag = g_embr + (size_t)bm0 * (NF * EMBED) + (size_t)i * EMBED;
    const float* Bg = g_Wt + (size_t)p * (EMBED * EMBED) + (size_t)bn0 * EMBED;

    // ldmatrix per-lane addressing, split into row part + swizzled column part.
    // Stored layout: byte (r, cb) lives at  r*128 + (cb ^ ((r&7)<<4)).
    // Per-use column byte = colbyte_lo (0 or 16) + ks*32; all fit in bits [6:4],
    // so compose with XOR against the row swizzle.
    uint32_t arow[4], axor[4];
    {
        const int rbase = wm * 64 + (lane & 15);
        const uint32_t ac = (uint32_t)(lane >> 4) * 16;   // 0 or 16
        #pragma unroll
        for (int mi = 0; mi < 4; ++mi) {
            const int r = rbase + mi * 16;
            arow[mi] = sb + OFF_A0 + (uint32_t)(r * 128);
            axor[mi] = ((uint32_t)(r & 7) << 4) ^ ac;
        }
    }
    uint32_t brow[2], bxor[2];
    {
        const int rr = ((lane >> 4) & 1) * 8 + (lane & 7);
        const uint32_t bc = (uint32_t)((lane >> 3) & 1) * 16;
        #pragma unroll
        for (int nh = 0; nh < 2; ++nh) {
            const int r = wn * 32 + nh * 16 + rr;
            brow[nh] = sb + OFF_B0 + (uint32_t)(r * 128);
            bxor[nh] = ((uint32_t)(r & 7) << 4) ^ bc;
        }
    }

    float acc[4][4][4];
    #pragma unroll
    for (int mi = 0; mi < 4; ++mi)
        #pragma unroll
        for (int ni = 0; ni < 4; ++ni)
            #pragma unroll
            for (int r = 0; r < 4; ++r)
                acc[mi][ni][r] = 0.0f;

    // chunk loader: 128 rows x 32 floats each for A and B (4 float4 per thread each)
    auto load_chunk = [&](int s, int k0) {
        const uint32_t ab = sb + OFF_A0 + s * TILE_BYTES;
        #pragma unroll
        for (int it = 0; it < 4; ++it) {
            const int idx = tid + it * THREADS;
            const int r = idx >> 3, q = idx & 7;
            const uint32_t off = r * 128 + q * 16;
            cp_async16(ab + SWZ(off), Ag + (size_t)r * (NF * EMBED) + k0 + q * 4);
        }
        const uint32_t bb = sb + OFF_B0 + s * TILE_BYTES;
        #pragma unroll
        for (int it = 0; it < 4; ++it) {
            const int idx = tid + it * THREADS;
            const int r = idx >> 3, q = idx & 7;
            const uint32_t off = r * 128 + q * 16;
            cp_async16(bb + SWZ(off), Bg + (size_t)r * EMBED + k0 + q * 4);
        }
        cp_commit();
    };

    load_chunk(0, 0);

    #pragma unroll 1
    for (int kt = 0; kt < NCHUNK; ++kt) {
        if (kt + 1 < NCHUNK) {
            load_chunk((kt + 1) & 1, (kt + 1) * BK);
            asm volatile("cp.async.wait_group 1;\n" ::: "memory");
        } else {
            asm volatile("cp.async.wait_group 0;\n" ::: "memory");
        }
        __syncthreads();

        const uint32_t so = (kt & 1) * TILE_BYTES;

        #pragma unroll
        for (int ks = 0; ks < BK / 8; ++ks) {
            const uint32_t kb = (uint32_t)(ks * 32);

            uint32_t af[4][4];
            #pragma unroll
            for (int mi = 0; mi < 4; ++mi)
                ldm_x4(af[mi], arow[mi] + so + (axor[mi] ^ kb));

            uint32_t bf[2][4];
            #pragma unroll
            for (int nh = 0; nh < 2; ++nh)
                ldm_x4(bf[nh], brow[nh] + so + (bxor[nh] ^ kb));

            #pragma unroll
            for (int mi = 0; mi < 4; ++mi)
                #pragma unroll
                for (int ni = 0; ni < 4; ++ni)
                    mma_tf32(acc[mi][ni], af[mi],
                             bf[ni >> 1][(ni & 1) * 2], bf[ni >> 1][(ni & 1) * 2 + 1]);
        }
        __syncthreads();
    }

    // ---- epilogue: out[b,p,f] = acc * emb[b,j,f] + bias[p,f] ----
    const float* biasP = bias + (size_t)p * EMBED;
    const int g  = lane >> 2;
    const int t4 = lane & 3;

    #pragma unroll
    for (int mi = 0; mi < 4; ++mi) {
        const int r0 = bm0 + wm * 64 + mi * 16 + g;
        #pragma unroll
        for (int ni = 0; ni < 4; ++ni) {
            const int c = bn0 + wn * 32 + ni * 8 + t4 * 2;
            const float2 bb = *(const float2*)(biasP + c);
            #pragma unroll
            for (int h = 0; h < 2; ++h) {
                const int row = r0 + h * 8;
                const float2 q = *(const float2*)(emb + (size_t)row * (NF * EMBED)
                                                   + (size_t)j * EMBED + c);
                float2 v;
                v.x = acc[mi][ni][h * 2 + 0] * q.x + bb.x;
                v.y = acc[mi][ni][h * 2 + 1] * q.y + bb.y;
                *(float2*)(out + (size_t)row * (NPAIR * EMBED) + (size_t)p * EMBED + c) = v;
            }
        }
    }
}

// ---------------- launch ----------------
extern "C" void kernel_launch(void* const* d_in, const int* in_sizes, int n_in,
                              void* d_out, int out_size) {
    const float* emb    = (const float*)d_in[0];
    const float* weight = (const float*)d_in[1];
    const float* bias   = (const float*)d_in[2];
    float* out          = (float*)d_out;

    cudaFuncSetAttribute(bilinear_mma, cudaFuncAttributeMaxDynamicSharedMemorySize, SMEM_TOTAL);

    prep_weight<<<dim3(8, 8, NPAIR), dim3(32, 8)>>>(weight);
    prep_emb<<<8192, 256>>>((const float4*)emb);

    dim3 grid(BATCH / BM, EMBED / BN, NPAIR);
    bilinear_mma<<<grid, THREADS, SMEM_TOTAL>>>(emb, bias, out);
}

// round 6
// speedup vs baseline: 1.2622x; 1.2622x over previous
#include <cuda_runtime.h>
#include <cuda_bf16.h>
#include <cstdint>

// Problem constants
#define NUM_FIELDS 16
#define EMBED      256
#define BATCH      2048
#define NUM_PAIRS  120

// Tiling
#define BM 128
#define BN 128
#define BK 16
#define THREADS 256

#define A_STRIDE (BK + 4)   // 20 floats -> conflict-free fragment loads
#define B_STRIDE (BN + 4)   // 132 floats

// static scratch: tf32-pre-rounded copies (allocation-free rule: __device__ globals)
__device__ float g_Wr[(size_t)NUM_PAIRS * EMBED * EMBED];
__device__ float g_embr[(size_t)BATCH * NUM_FIELDS * EMBED];

__device__ __forceinline__ uint32_t smem_u32(const void* p) {
    return (uint32_t)__cvta_generic_to_shared(p);
}

__device__ __forceinline__ void cp_async16(uint32_t dst, const void* src) {
    asm volatile("cp.async.cg.shared.global [%0], [%1], 16;\n" :: "r"(dst), "l"(src));
}

__device__ __forceinline__ void cp_commit() {
    asm volatile("cp.async.commit_group;\n" ::: "memory");
}

__device__ __forceinline__ float tf32r(float f) {
    uint32_t r;
    asm("cvt.rna.tf32.f32 %0, %1;" : "=r"(r) : "f"(f));
    return __uint_as_float(r);
}

__device__ __forceinline__ void mma_tf32(float c[4], const uint32_t a[4], const uint32_t b[2]) {
    asm volatile(
        "mma.sync.aligned.m16n8k8.row.col.f32.tf32.tf32.f32 "
        "{%0,%1,%2,%3}, {%4,%5,%6,%7}, {%8,%9}, {%0,%1,%2,%3};\n"
        : "+f"(c[0]), "+f"(c[1]), "+f"(c[2]), "+f"(c[3])
        : "r"(a[0]), "r"(a[1]), "r"(a[2]), "r"(a[3]), "r"(b[0]), "r"(b[1]));
}

// ---------------- prep kernels: elementwise tf32 rounding (no transpose) ----
__global__ void prep_weight(const float4* __restrict__ w) {
    const size_t idx = (size_t)blockIdx.x * blockDim.x + threadIdx.x; // 1,966,080 float4
    float4 v = w[idx];
    v.x = tf32r(v.x); v.y = tf32r(v.y); v.z = tf32r(v.z); v.w = tf32r(v.w);
    reinterpret_cast<float4*>(g_Wr)[idx] = v;
}

__global__ void prep_emb(const float4* __restrict__ e) {
    const size_t idx = (size_t)blockIdx.x * blockDim.x + threadIdx.x; // 2,097,152 float4
    float4 v = e[idx];
    v.x = tf32r(v.x); v.y = tf32r(v.y); v.z = tf32r(v.z); v.w = tf32r(v.w);
    reinterpret_cast<float4*>(g_embr)[idx] = v;
}

// ---------------- main kernel (R2 structure, CVT-free inner loop) ----------
__global__ void __launch_bounds__(THREADS, 2)
bilinear_kernel(const float* __restrict__ emb,
                const float* __restrict__ bias,
                float* __restrict__ out)
{
    const int p   = blockIdx.z;
    const int bm0 = blockIdx.x * BM;
    const int bn0 = blockIdx.y * BN;

    // pair p -> (i, j) of triu_indices(16, k=1)
    int i = 0, rem = p;
    while (rem >= (NUM_FIELDS - 1) - i) { rem -= (NUM_FIELDS - 1) - i; ++i; }
    const int j = i + 1 + rem;

    __shared__ uint32_t As[2][BM][A_STRIDE];
    __shared__ uint32_t Bs[2][BK][B_STRIDE];

    const int tid  = threadIdx.x;
    const int lane = tid & 31;
    const int warp = tid >> 5;
    const int wm   = warp & 1;    // 0..1  (64-row slab)
    const int wn   = warp >> 1;   // 0..3  (32-col slab)
    const int g    = lane >> 2;   // 0..7
    const int t4   = lane & 3;    // 0..3

    const float* Aglob = g_embr + (size_t)bm0 * (NUM_FIELDS * EMBED) + (size_t)i * EMBED;
    const float* Bglob = g_Wr + (size_t)p * (EMBED * EMBED) + bn0;

    float acc[4][4][4];
    #pragma unroll
    for (int mi = 0; mi < 4; ++mi)
        #pragma unroll
        for (int ni = 0; ni < 4; ++ni)
            #pragma unroll
            for (int r = 0; r < 4; ++r)
                acc[mi][ni][r] = 0.0f;

    // ---- async tile loaders -------------------------------------------------
    auto load_tiles = [&](int buf, int k0) {
        #pragma unroll
        for (int it = 0; it < 2; ++it) {
            int idx = tid + it * THREADS;
            int m   = idx >> 2;          // 0..127
            int kq  = idx & 3;           // float4 in k
            cp_async16(smem_u32(&As[buf][m][kq * 4]),
                       Aglob + (size_t)m * (NUM_FIELDS * EMBED) + k0 + kq * 4);
        }
        #pragma unroll
        for (int it = 0; it < 2; ++it) {
            int idx = tid + it * THREADS;
            int kr  = idx >> 5;          // 0..15
            int nq  = idx & 31;          // float4 in n
            cp_async16(smem_u32(&Bs[buf][kr][nq * 4]),
                       Bglob + (size_t)(k0 + kr) * EMBED + nq * 4);
        }
    };

    const int NK = EMBED / BK;   // 16

    load_tiles(0, 0);
    cp_commit();

    for (int kt = 0; kt < NK; ++kt) {
        if (kt + 1 < NK) {
            load_tiles((kt + 1) & 1, (kt + 1) * BK);
            cp_commit();
            asm volatile("cp.async.wait_group 1;\n" ::: "memory");
        } else {
            asm volatile("cp.async.wait_group 0;\n" ::: "memory");
        }
        __syncthreads();

        const int buf = kt & 1;

        #pragma unroll
        for (int ks = 0; ks < BK / 8; ++ks) {
            uint32_t afrag[4][4];
            #pragma unroll
            for (int mi = 0; mi < 4; ++mi) {
                const int rm = wm * 64 + mi * 16;
                afrag[mi][0] = As[buf][rm + g    ][ks * 8 + t4    ];
                afrag[mi][1] = As[buf][rm + g + 8][ks * 8 + t4    ];
                afrag[mi][2] = As[buf][rm + g    ][ks * 8 + t4 + 4];
                afrag[mi][3] = As[buf][rm + g + 8][ks * 8 + t4 + 4];
            }
            uint32_t bfrag[4][2];
            #pragma unroll
            for (int ni = 0; ni < 4; ++ni) {
                const int cn = wn * 32 + ni * 8 + g;
                bfrag[ni][0] = Bs[buf][ks * 8 + t4    ][cn];
                bfrag[ni][1] = Bs[buf][ks * 8 + t4 + 4][cn];
            }
            #pragma unroll
            for (int mi = 0; mi < 4; ++mi)
                #pragma unroll
                for (int ni = 0; ni < 4; ++ni)
                    mma_tf32(acc[mi][ni], afrag[mi], bfrag[ni]);
        }
        __syncthreads();
    }

    // ---- epilogue: out[b,p,f] = acc * emb[b,j,f] + bias[p,f] ---------------
    const float* biasP = bias + (size_t)p * EMBED;

    #pragma unroll
    for (int mi = 0; mi < 4; ++mi) {
        const int r0 = bm0 + wm * 64 + mi * 16 + g;
        #pragma unroll
        for (int ni = 0; ni < 4; ++ni) {
            const int c = bn0 + wn * 32 + ni * 8 + t4 * 2;
            const float2 bb = *(const float2*)(biasP + c);
            #pragma unroll
            for (int h = 0; h < 2; ++h) {
                const int row = r0 + h * 8;
                const float2 q = *(const float2*)(emb + (size_t)row * (NUM_FIELDS * EMBED)
                                                   + (size_t)j * EMBED + c);
                float2 v;
                v.x = acc[mi][ni][h * 2 + 0] * q.x + bb.x;
                v.y = acc[mi][ni][h * 2 + 1] * q.y + bb.y;
                *(float2*)(out + (size_t)row * (NUM_PAIRS * EMBED) + (size_t)p * EMBED + c) = v;
            }
        }
    }
}

extern "C" void kernel_launch(void* const* d_in, const int* in_sizes, int n_in,
                              void* d_out, int out_size) {
    const float* emb    = (const float*)d_in[0];
    const float* weight = (const float*)d_in[1];
    const float* bias   = (const float*)d_in[2];
    float* out          = (float*)d_out;

    // elementwise tf32 pre-rounding (no layout change)
    prep_weight<<<7680, 256>>>((const float4*)weight);  // 120*256*256/4 = 1,966,080
    prep_emb<<<8192, 256>>>((const float4*)emb);        // 2048*16*256/4 = 2,097,152

    dim3 grid(BATCH / BM, EMBED / BN, NUM_PAIRS);
    dim3 block(THREADS);
    bilinear_kernel<<<grid, block>>>(emb, bias, out);
}

// round 7
// speedup vs baseline: 1.3226x; 1.0478x over previous
#include <cuda_runtime.h>
#include <cstdint>

// Problem constants
#define NUM_FIELDS 16
#define EMBED      256
#define BATCH      2048
#define NUM_PAIRS  120

// Tiling: 128x64 CTA tile, 32x32 warp tile, 3 CTAs/SM
#define BM 128
#define BN 64
#define BK 16
#define THREADS 256

#define A_STRIDE (BK + 4)   // 20: banks g*20+t4 all distinct -> conflict-free
#define B_STRIDE (BN + 8)   // 72: stride%32==8 -> conflict-free across t4 groups

__device__ __forceinline__ uint32_t smem_u32(const void* p) {
    return (uint32_t)__cvta_generic_to_shared(p);
}

__device__ __forceinline__ void cp_async16(uint32_t dst, const void* src) {
    asm volatile("cp.async.cg.shared.global [%0], [%1], 16;\n" :: "r"(dst), "l"(src));
}

__device__ __forceinline__ void cp_commit() {
    asm volatile("cp.async.commit_group;\n" ::: "memory");
}

__device__ __forceinline__ uint32_t f2tf32(float f) {
    uint32_t r;
    asm("cvt.rna.tf32.f32 %0, %1;" : "=r"(r) : "f"(f));
    return r;
}

__device__ __forceinline__ void mma_tf32(float c[4], const uint32_t a[4], const uint32_t b[2]) {
    asm volatile(
        "mma.sync.aligned.m16n8k8.row.col.f32.tf32.tf32.f32 "
        "{%0,%1,%2,%3}, {%4,%5,%6,%7}, {%8,%9}, {%0,%1,%2,%3};\n"
        : "+f"(c[0]), "+f"(c[1]), "+f"(c[2]), "+f"(c[3])
        : "r"(a[0]), "r"(a[1]), "r"(a[2]), "r"(a[3]), "r"(b[0]), "r"(b[1]));
}

__global__ void __launch_bounds__(THREADS, 3)
bilinear_kernel(const float* __restrict__ emb,
                const float* __restrict__ weight,
                const float* __restrict__ bias,
                float* __restrict__ out)
{
    const int p   = blockIdx.z;
    const int bm0 = blockIdx.x * BM;
    const int bn0 = blockIdx.y * BN;

    // pair p -> (i, j) of triu_indices(16, k=1)
    int i = 0, rem = p;
    while (rem >= (NUM_FIELDS - 1) - i) { rem -= (NUM_FIELDS - 1) - i; ++i; }
    const int j = i + 1 + rem;

    __shared__ float As[2][BM][A_STRIDE];
    __shared__ float Bs[2][BK][B_STRIDE];

    const int tid  = threadIdx.x;
    const int lane = tid & 31;
    const int warp = tid >> 5;
    const int wm   = warp & 3;    // 0..3  (32-row slab)
    const int wn   = warp >> 2;   // 0..1  (32-col slab)
    const int g    = lane >> 2;   // 0..7
    const int t4   = lane & 3;    // 0..3

    const float* Aglob = emb + (size_t)bm0 * (NUM_FIELDS * EMBED) + (size_t)i * EMBED;
    const float* Bglob = weight + (size_t)p * (EMBED * EMBED) + bn0;

    float acc[2][4][4];
    #pragma unroll
    for (int mi = 0; mi < 2; ++mi)
        #pragma unroll
        for (int ni = 0; ni < 4; ++ni)
            #pragma unroll
            for (int r = 0; r < 4; ++r)
                acc[mi][ni][r] = 0.0f;

    // ---- async tile loaders -------------------------------------------------
    // A tile: 128 rows x 16 floats = 512 float4 -> 2 per thread
    // B tile: 16 rows x 64 floats  = 256 float4 -> 1 per thread
    auto load_tiles = [&](int buf, int k0) {
        #pragma unroll
        for (int it = 0; it < 2; ++it) {
            int idx = tid + it * THREADS;
            int m   = idx >> 2;          // 0..127
            int kq  = idx & 3;           // float4 in k
            cp_async16(smem_u32(&As[buf][m][kq * 4]),
                       Aglob + (size_t)m * (NUM_FIELDS * EMBED) + k0 + kq * 4);
        }
        {
            int kr = tid >> 4;           // 0..15
            int nq = tid & 15;           // 0..15 float4 in n
            cp_async16(smem_u32(&Bs[buf][kr][nq * 4]),
                       Bglob + (size_t)(k0 + kr) * EMBED + nq * 4);
        }
    };

    const int NK = EMBED / BK;   // 16

    load_tiles(0, 0);
    cp_commit();

    for (int kt = 0; kt < NK; ++kt) {
        if (kt + 1 < NK) {
            load_tiles((kt + 1) & 1, (kt + 1) * BK);
            cp_commit();
            asm volatile("cp.async.wait_group 1;\n" ::: "memory");
        } else {
            asm volatile("cp.async.wait_group 0;\n" ::: "memory");
        }
        __syncthreads();

        const int buf = kt & 1;

        #pragma unroll
        for (int ks = 0; ks < BK / 8; ++ks) {
            uint32_t afrag[2][4];
            #pragma unroll
            for (int mi = 0; mi < 2; ++mi) {
                const int rm = wm * 32 + mi * 16;
                afrag[mi][0] = f2tf32(As[buf][rm + g    ][ks * 8 + t4    ]);
                afrag[mi][1] = f2tf32(As[buf][rm + g + 8][ks * 8 + t4    ]);
                afrag[mi][2] = f2tf32(As[buf][rm + g    ][ks * 8 + t4 + 4]);
                afrag[mi][3] = f2tf32(As[buf][rm + g + 8][ks * 8 + t4 + 4]);
            }
            uint32_t bfrag[4][2];
            #pragma unroll
            for (int ni = 0; ni < 4; ++ni) {
                const int cn = wn * 32 + ni * 8 + g;
                bfrag[ni][0] = f2tf32(Bs[buf][ks * 8 + t4    ][cn]);
                bfrag[ni][1] = f2tf32(Bs[buf][ks * 8 + t4 + 4][cn]);
            }
            #pragma unroll
            for (int mi = 0; mi < 2; ++mi)
                #pragma unroll
                for (int ni = 0; ni < 4; ++ni)
                    mma_tf32(acc[mi][ni], afrag[mi], bfrag[ni]);
        }
        __syncthreads();
    }

    // ---- epilogue: out[b,p,f] = acc * emb[b,j,f] + bias[p,f] ---------------
    const float* biasP = bias + (size_t)p * EMBED;

    #pragma unroll
    for (int mi = 0; mi < 2; ++mi) {
        const int r0 = bm0 + wm * 32 + mi * 16 + g;
        #pragma unroll
        for (int ni = 0; ni < 4; ++ni) {
            const int c = bn0 + wn * 32 + ni * 8 + t4 * 2;
            const float2 bb = *(const float2*)(biasP + c);
            #pragma unroll
            for (int h = 0; h < 2; ++h) {
                const int row = r0 + h * 8;
                const float2 q = *(const float2*)(emb + (size_t)row * (NUM_FIELDS * EMBED)
                                                   + (size_t)j * EMBED + c);
                float2 v;
                v.x = acc[mi][ni][h * 2 + 0] * q.x + bb.x;
                v.y = acc[mi][ni][h * 2 + 1] * q.y + bb.y;
                *(float2*)(out + (size_t)row * (NUM_PAIRS * EMBED) + (size_t)p * EMBED + c) = v;
            }
        }
    }
}

extern "C" void kernel_launch(void* const* d_in, const int* in_sizes, int n_in,
                              void* d_out, int out_size) {
    const float* emb    = (const float*)d_in[0];
    const float* weight = (const float*)d_in[1];
    const float* bias   = (const float*)d_in[2];
    float* out          = (float*)d_out;

    dim3 grid(BATCH / BM, EMBED / BN, NUM_PAIRS);   // (16, 4, 120)
    dim3 block(THREADS);
    bilinear_kernel<<<grid, block>>>(emb, weight, bias, out);
}

// round 8
// speedup vs baseline: 1.3321x; 1.0072x over previous
#include <cuda_runtime.h>
#include <cstdint>

// Problem constants
#define NUM_FIELDS 16
#define EMBED      256
#define BATCH      2048
#define NUM_PAIRS  120

// Tiling: CTA 128x256 (full N), warp tile 64x64, 8 warps (2 x 4)
#define BM 128
#define BN 256
#define BK 16
#define THREADS 256

#define A_STRIDE (BK + 4)    // 20 floats
#define B_STRIDE (BN + 8)    // 264 floats: %32==8 -> conflict-free fragment loads

// tf32-pre-rounded copies (allocation-free rule: __device__ globals)
__device__ float g_Wr[(size_t)NUM_PAIRS * EMBED * EMBED];
__device__ float g_embr[(size_t)BATCH * NUM_FIELDS * EMBED];

__device__ __forceinline__ uint32_t smem_u32(const void* p) {
    return (uint32_t)__cvta_generic_to_shared(p);
}
__device__ __forceinline__ void cp_async16(uint32_t dst, const void* src) {
    asm volatile("cp.async.cg.shared.global [%0], [%1], 16;\n" :: "r"(dst), "l"(src));
}
__device__ __forceinline__ void cp_commit() {
    asm volatile("cp.async.commit_group;\n" ::: "memory");
}
__device__ __forceinline__ float tf32r(float f) {
    uint32_t r;
    asm("cvt.rna.tf32.f32 %0, %1;" : "=r"(r) : "f"(f));
    return __uint_as_float(r);
}
__device__ __forceinline__ void mma_tf32(float c[4], const uint32_t a[4], const uint32_t b[2]) {
    asm volatile(
        "mma.sync.aligned.m16n8k8.row.col.f32.tf32.tf32.f32 "
        "{%0,%1,%2,%3}, {%4,%5,%6,%7}, {%8,%9}, {%0,%1,%2,%3};\n"
        : "+f"(c[0]), "+f"(c[1]), "+f"(c[2]), "+f"(c[3])
        : "r"(a[0]), "r"(a[1]), "r"(a[2]), "r"(a[3]), "r"(b[0]), "r"(b[1]));
}

// ---------------- prep kernels: elementwise tf32 rounding ----------------
__global__ void prep_weight(const float4* __restrict__ w) {
    const size_t idx = (size_t)blockIdx.x * blockDim.x + threadIdx.x;
    float4 v = w[idx];
    v.x = tf32r(v.x); v.y = tf32r(v.y); v.z = tf32r(v.z); v.w = tf32r(v.w);
    reinterpret_cast<float4*>(g_Wr)[idx] = v;
}
__global__ void prep_emb(const float4* __restrict__ e) {
    const size_t idx = (size_t)blockIdx.x * blockDim.x + threadIdx.x;
    float4 v = e[idx];
    v.x = tf32r(v.x); v.y = tf32r(v.y); v.z = tf32r(v.z); v.w = tf32r(v.w);
    reinterpret_cast<float4*>(g_embr)[idx] = v;
}

// ---------------- main kernel ----------------
__global__ void __launch_bounds__(THREADS, 1)
bilinear_kernel(const float* __restrict__ emb,
                const float* __restrict__ bias,
                float* __restrict__ out)
{
    const int p   = blockIdx.y;
    const int bm0 = blockIdx.x * BM;

    // pair p -> (i, j) of triu_indices(16, k=1)
    int i = 0, rem = p;
    while (rem >= (NUM_FIELDS - 1) - i) { rem -= (NUM_FIELDS - 1) - i; ++i; }
    const int j = i + 1 + rem;

    __shared__ uint32_t As[2][BM][A_STRIDE];
    __shared__ uint32_t Bs[2][BK][B_STRIDE];

    const int tid  = threadIdx.x;
    const int lane = tid & 31;
    const int warp = tid >> 5;
    const int wm   = warp >> 2;   // 0..1  (64-row slab)
    const int wn   = warp & 3;    // 0..3  (64-col slab)
    const int g    = lane >> 2;   // 0..7
    const int t4   = lane & 3;    // 0..3

    const float* Aglob = g_embr + (size_t)bm0 * (NUM_FIELDS * EMBED) + (size_t)i * EMBED;
    const float* Bglob = g_Wr + (size_t)p * (EMBED * EMBED);

    float acc[4][8][4];
    #pragma unroll
    for (int mi = 0; mi < 4; ++mi)
        #pragma unroll
        for (int ni = 0; ni < 8; ++ni)
            #pragma unroll
            for (int r = 0; r < 4; ++r)
                acc[mi][ni][r] = 0.0f;

    // ---- async tile loaders -------------------------------------------------
    // A tile: 128 rows x 16 floats = 512 float4 -> 2 per thread
    // B tile: 16 rows x 256 floats = 1024 float4 -> 4 per thread
    auto load_tiles = [&](int buf, int k0) {
        #pragma unroll
        for (int it = 0; it < 2; ++it) {
            int idx = tid + it * THREADS;
            int m   = idx >> 2;
            int kq  = idx & 3;
            cp_async16(smem_u32(&As[buf][m][kq * 4]),
                       Aglob + (size_t)m * (NUM_FIELDS * EMBED) + k0 + kq * 4);
        }
        {
            int kr = tid >> 4;            // 0..15
            int n0 = tid & 15;            // 0..15
            #pragma unroll
            for (int it = 0; it < 4; ++it) {
                int nq = n0 + it * 16;    // 0..63 float4 in n
                cp_async16(smem_u32(&Bs[buf][kr][nq * 4]),
                           Bglob + (size_t)(k0 + kr) * EMBED + nq * 4);
            }
        }
    };

    const int NK = EMBED / BK;   // 16

    load_tiles(0, 0);
    cp_commit();

    for (int kt = 0; kt < NK; ++kt) {
        if (kt + 1 < NK) {
            load_tiles((kt + 1) & 1, (kt + 1) * BK);
            cp_commit();
            asm volatile("cp.async.wait_group 1;\n" ::: "memory");
        } else {
            asm volatile("cp.async.wait_group 0;\n" ::: "memory");
        }
        __syncthreads();

        const int buf = kt & 1;

        #pragma unroll
        for (int ks = 0; ks < BK / 8; ++ks) {
            uint32_t afrag[4][4];
            #pragma unroll
            for (int mi = 0; mi < 4; ++mi) {
                const int rm = wm * 64 + mi * 16;
                afrag[mi][0] = As[buf][rm + g    ][ks * 8 + t4    ];
                afrag[mi][1] = As[buf][rm + g + 8][ks * 8 + t4    ];
                afrag[mi][2] = As[buf][rm + g    ][ks * 8 + t4 + 4];
                afrag[mi][3] = As[buf][rm + g + 8][ks * 8 + t4 + 4];
            }
            uint32_t bfrag[8][2];
            #pragma unroll
            for (int ni = 0; ni < 8; ++ni) {
                const int cn = wn * 64 + ni * 8 + g;
                bfrag[ni][0] = Bs[buf][ks * 8 + t4    ][cn];
                bfrag[ni][1] = Bs[buf][ks * 8 + t4 + 4][cn];
            }
            #pragma unroll
            for (int mi = 0; mi < 4; ++mi)
                #pragma unroll
                for (int ni = 0; ni < 8; ++ni)
                    mma_tf32(acc[mi][ni], afrag[mi], bfrag[ni]);
        }
        __syncthreads();
    }

    // ---- epilogue: out[b,p,f] = acc * emb[b,j,f] + bias[p,f] ---------------
    const float* biasP = bias + (size_t)p * EMBED;

    #pragma unroll
    for (int mi = 0; mi < 4; ++mi) {
        const int r0 = bm0 + wm * 64 + mi * 16 + g;
        #pragma unroll
        for (int ni = 0; ni < 8; ++ni) {
            const int c = wn * 64 + ni * 8 + t4 * 2;
            const float2 bb = *(const float2*)(biasP + c);
            #pragma unroll
            for (int h = 0; h < 2; ++h) {
                const int row = r0 + h * 8;
                const float2 q = *(const float2*)(emb + (size_t)row * (NUM_FIELDS * EMBED)
                                                   + (size_t)j * EMBED + c);
                float2 v;
                v.x = acc[mi][ni][h * 2 + 0] * q.x + bb.x;
                v.y = acc[mi][ni][h * 2 + 1] * q.y + bb.y;
                *(float2*)(out + (size_t)row * (NUM_PAIRS * EMBED) + (size_t)p * EMBED + c) = v;
            }
        }
    }
}

extern "C" void kernel_launch(void* const* d_in, const int* in_sizes, int n_in,
                              void* d_out, int out_size) {
    const float* emb    = (const float*)d_in[0];
    const float* weight = (const float*)d_in[1];
    const float* bias   = (const float*)d_in[2];
    float* out          = (float*)d_out;

    prep_weight<<<7680, 256>>>((const float4*)weight);  // 120*256*256/4
    prep_emb<<<8192, 256>>>((const float4*)emb);        // 2048*16*256/4

    dim3 grid(BATCH / BM, NUM_PAIRS);   // (16, 120)
    bilinear_kernel<<<grid, THREADS>>>(emb, bias, out);
}

// round 9
// speedup vs baseline: 1.9598x; 1.4713x over previous
#include <cuda_runtime.h>
#include <cuda_fp16.h>
#include <cstdint>

// Problem constants
#define NUM_FIELDS 16
#define EMBED      256
#define BATCH      2048
#define NUM_PAIRS  120

// Tiling: CTA 128x128, warp tile 64x32 (2x4 warps), BK=32, fp16 m16n8k16
#define BM 128
#define BN 128
#define BK 32
#define THREADS 256

#define A_STRIDE 40   // halfs; 80B = 20 banks -> banks 20g+t4 all distinct
#define B_STRIDE 40

// fp16 copies (allocation-free rule: __device__ globals)
__device__ __half g_Wt[(size_t)NUM_PAIRS * EMBED * EMBED];   // W^T: [p][f][e]
__device__ __half g_embh[(size_t)BATCH * NUM_FIELDS * EMBED];

__device__ __forceinline__ uint32_t smem_u32(const void* p) {
    return (uint32_t)__cvta_generic_to_shared(p);
}
__device__ __forceinline__ void cp_async16(uint32_t dst, const void* src) {
    asm volatile("cp.async.cg.shared.global [%0], [%1], 16;\n" :: "r"(dst), "l"(src));
}
__device__ __forceinline__ void cp_commit() {
    asm volatile("cp.async.commit_group;\n" ::: "memory");
}
__device__ __forceinline__ void mma_f16(float c[4], const uint32_t a[4], const uint32_t b[2]) {
    asm volatile(
        "mma.sync.aligned.m16n8k16.row.col.f32.f16.f16.f32 "
        "{%0,%1,%2,%3}, {%4,%5,%6,%7}, {%8,%9}, {%0,%1,%2,%3};\n"
        : "+f"(c[0]), "+f"(c[1]), "+f"(c[2]), "+f"(c[3])
        : "r"(a[0]), "r"(a[1]), "r"(a[2]), "r"(a[3]), "r"(b[0]), "r"(b[1]));
}

// ---------------- prep kernels ----------------
// Transpose + fp16 convert:  g_Wt[p][f][e] = (half) W[p][e][f]
__global__ void prep_weight(const float* __restrict__ w) {
    __shared__ float t[32][33];
    const int p  = blockIdx.z;
    const int f0 = blockIdx.x * 32;
    const int e0 = blockIdx.y * 32;
    const int tx = threadIdx.x, ty = threadIdx.y;   // 32 x 8
    const float* W = w + (size_t)p * EMBED * EMBED;
    #pragma unroll
    for (int r = 0; r < 4; ++r)
        t[ty + 8 * r][tx] = W[(size_t)(e0 + ty + 8 * r) * EMBED + f0 + tx];
    __syncthreads();
    __half* Wt = g_Wt + (size_t)p * EMBED * EMBED;
    #pragma unroll
    for (int r = 0; r < 4; ++r)
        Wt[(size_t)(f0 + ty + 8 * r) * EMBED + e0 + tx] = __float2half_rn(t[tx][ty + 8 * r]);
}

// fp16 convert emb
__global__ void prep_emb(const float4* __restrict__ e) {
    const size_t idx = (size_t)blockIdx.x * blockDim.x + threadIdx.x; // 2,097,152 float4
    float4 v = e[idx];
    __half2 lo = __floats2half2_rn(v.x, v.y);
    __half2 hi = __floats2half2_rn(v.z, v.w);
    reinterpret_cast<__half2*>(g_embh)[idx * 2 + 0] = lo;
    reinterpret_cast<__half2*>(g_embh)[idx * 2 + 1] = hi;
}

// ---------------- main kernel ----------------
__global__ void __launch_bounds__(THREADS, 2)
bilinear_kernel(const float* __restrict__ emb,
                const float* __restrict__ bias,
                float* __restrict__ out)
{
    const int p   = blockIdx.z;
    const int bm0 = blockIdx.x * BM;
    const int bn0 = blockIdx.y * BN;

    // pair p -> (i, j) of triu_indices(16, k=1)
    int i = 0, rem = p;
    while (rem >= (NUM_FIELDS - 1) - i) { rem -= (NUM_FIELDS - 1) - i; ++i; }
    const int j = i + 1 + rem;

    __shared__ __half As[2][BM][A_STRIDE];
    __shared__ __half Bs[2][BN][B_STRIDE];   // [n][k] layout (W^T rows)

    const int tid  = threadIdx.x;
    const int lane = tid & 31;
    const int warp = tid >> 5;
    const int wm   = warp >> 2;   // 0..1  (64-row slab)
    const int wn   = warp & 3;    // 0..3  (32-col slab)
    const int g    = lane >> 2;   // 0..7
    const int t4   = lane & 3;    // 0..3

    const __half* Aglob = g_embh + (size_t)bm0 * (NUM_FIELDS * EMBED) + (size_t)i * EMBED;
    const __half* Bglob = g_Wt + (size_t)p * (EMBED * EMBED) + (size_t)bn0 * EMBED;

    float acc[4][4][4];
    #pragma unroll
    for (int mi = 0; mi < 4; ++mi)
        #pragma unroll
        for (int ni = 0; ni < 4; ++ni)
            #pragma unroll
            for (int r = 0; r < 4; ++r)
                acc[mi][ni][r] = 0.0f;

    // ---- async tile loaders: 128 rows x 32 halfs = 512 x 16B each ---------
    auto load_tiles = [&](int buf, int k0) {
        #pragma unroll
        for (int it = 0; it < 2; ++it) {
            int idx = tid + it * THREADS;
            int m   = idx >> 2;          // 0..127
            int q   = idx & 3;           // 8-half chunk
            cp_async16(smem_u32(&As[buf][m][q * 8]),
                       Aglob + (size_t)m * (NUM_FIELDS * EMBED) + k0 + q * 8);
        }
        #pragma unroll
        for (int it = 0; it < 2; ++it) {
            int idx = tid + it * THREADS;
            int n   = idx >> 2;          // 0..127
            int q   = idx & 3;
            cp_async16(smem_u32(&Bs[buf][n][q * 8]),
                       Bglob + (size_t)n * EMBED + k0 + q * 8);
        }
    };

    const int NK = EMBED / BK;   // 8

    load_tiles(0, 0);
    cp_commit();

    for (int kt = 0; kt < NK; ++kt) {
        if (kt + 1 < NK) {
            load_tiles((kt + 1) & 1, (kt + 1) * BK);
            cp_commit();
            asm volatile("cp.async.wait_group 1;\n" ::: "memory");
        } else {
            asm volatile("cp.async.wait_group 0;\n" ::: "memory");
        }
        __syncthreads();

        const int buf = kt & 1;

        #pragma unroll
        for (int ks = 0; ks < BK / 16; ++ks) {
            const int kk = ks * 16;

            uint32_t afrag[4][4];
            #pragma unroll
            for (int mi = 0; mi < 4; ++mi) {
                const int rm = wm * 64 + mi * 16;
                afrag[mi][0] = *(const uint32_t*)&As[buf][rm + g    ][kk + 2 * t4    ];
                afrag[mi][1] = *(const uint32_t*)&As[buf][rm + g + 8][kk + 2 * t4    ];
                afrag[mi][2] = *(const uint32_t*)&As[buf][rm + g    ][kk + 2 * t4 + 8];
                afrag[mi][3] = *(const uint32_t*)&As[buf][rm + g + 8][kk + 2 * t4 + 8];
            }
            uint32_t bfrag[4][2];
            #pragma unroll
            for (int ni = 0; ni < 4; ++ni) {
                const int cn = wn * 32 + ni * 8 + g;
                bfrag[ni][0] = *(const uint32_t*)&Bs[buf][cn][kk + 2 * t4    ];
                bfrag[ni][1] = *(const uint32_t*)&Bs[buf][cn][kk + 2 * t4 + 8];
            }
            #pragma unroll
            for (int mi = 0; mi < 4; ++mi)
                #pragma unroll
                for (int ni = 0; ni < 4; ++ni)
                    mma_f16(acc[mi][ni], afrag[mi], bfrag[ni]);
        }
        __syncthreads();
    }

    // ---- epilogue: out[b,p,f] = acc * emb[b,j,f] + bias[p,f] ---------------
    const float* biasP = bias + (size_t)p * EMBED;

    #pragma unroll
    for (int mi = 0; mi < 4; ++mi) {
        const int r0 = bm0 + wm * 64 + mi * 16 + g;
        #pragma unroll
        for (int ni = 0; ni < 4; ++ni) {
            const int c = bn0 + wn * 32 + ni * 8 + t4 * 2;
            const float2 bb = *(const float2*)(biasP + c);
            #pragma unroll
            for (int h = 0; h < 2; ++h) {
                const int row = r0 + h * 8;
                const float2 q = *(const float2*)(emb + (size_t)row * (NUM_FIELDS * EMBED)
                                                   + (size_t)j * EMBED + c);
                float2 v;
                v.x = acc[mi][ni][h * 2 + 0] * q.x + bb.x;
                v.y = acc[mi][ni][h * 2 + 1] * q.y + bb.y;
                *(float2*)(out + (size_t)row * (NUM_PAIRS * EMBED) + (size_t)p * EMBED + c) = v;
            }
        }
    }
}

extern "C" void kernel_launch(void* const* d_in, const int* in_sizes, int n_in,
                              void* d_out, int out_size) {
    const float* emb    = (const float*)d_in[0];
    const float* weight = (const float*)d_in[1];
    const float* bias   = (const float*)d_in[2];
    float* out          = (float*)d_out;

    prep_weight<<<dim3(8, 8, NUM_PAIRS), dim3(32, 8)>>>(weight);
    prep_emb<<<8192, 256>>>((const float4*)emb);

    dim3 grid(BATCH / BM, EMBED / BN, NUM_PAIRS);   // (16, 2, 120)
    bilinear_kernel<<<grid, THREADS>>>(emb, bias, out);
}

// round 10
// speedup vs baseline: 2.1584x; 1.1013x over previous
#include <cuda_runtime.h>
#include <cuda_fp16.h>
#include <cstdint>

// Problem constants
#define NUM_FIELDS 16
#define EMBED      256
#define BATCH      2048
#define NUM_PAIRS  120

// Tiling: CTA 128x128, warp tile 64x32 (2x4 warps), BK=64, fp16 m16n8k16
#define BM 128
#define BN 128
#define BK 64
#define THREADS 256

#define STRIDE 72                 // halfs; bank = (36r + ...) -> frag banks 4g+t4 distinct
#define TILE_HALFS (128 * STRIDE) // 9216 halfs per buffer per operand
#define SMEM_BYTES (4 * TILE_HALFS * 2)   // A0,A1,B0,B1 = 73728 B

// fp16 copies (allocation-free rule: __device__ globals)
__device__ __half g_Wt[(size_t)NUM_PAIRS * EMBED * EMBED];   // W^T: [p][f][e]
__device__ __half g_embh[(size_t)BATCH * NUM_FIELDS * EMBED];

__device__ __forceinline__ uint32_t smem_u32(const void* p) {
    return (uint32_t)__cvta_generic_to_shared(p);
}
__device__ __forceinline__ void cp_async16(uint32_t dst, const void* src) {
    asm volatile("cp.async.cg.shared.global [%0], [%1], 16;\n" :: "r"(dst), "l"(src));
}
__device__ __forceinline__ void cp_commit() {
    asm volatile("cp.async.commit_group;\n" ::: "memory");
}
__device__ __forceinline__ void mma_f16(float c[4], const uint32_t a[4], const uint32_t b[2]) {
    asm volatile(
        "mma.sync.aligned.m16n8k16.row.col.f32.f16.f16.f32 "
        "{%0,%1,%2,%3}, {%4,%5,%6,%7}, {%8,%9}, {%0,%1,%2,%3};\n"
        : "+f"(c[0]), "+f"(c[1]), "+f"(c[2]), "+f"(c[3])
        : "r"(a[0]), "r"(a[1]), "r"(a[2]), "r"(a[3]), "r"(b[0]), "r"(b[1]));
}

// ---------------- fused prep kernel ----------------
// Blocks [0, 7680):  W^T fp16 transpose tiles (32x32 per block)
// Blocks [7680, 9728): emb fp16 convert (1024 float4 per block)
#define WBLOCKS 7680
#define EBLOCKS 2048

__global__ void prep_all(const float* __restrict__ w, const float4* __restrict__ e) {
    __shared__ float t[32][33];
    const int b = blockIdx.x;
    const int tid = threadIdx.x;

    if (b < WBLOCKS) {
        const int p   = b >> 6;           // 64 tiles per pair (8x8)
        const int til = b & 63;
        const int f0  = (til & 7) * 32;
        const int e0  = (til >> 3) * 32;
        const int tx = tid & 31, ty = tid >> 5;   // 32 x 8
        const float* W = w + (size_t)p * EMBED * EMBED;
        #pragma unroll
        for (int r = 0; r < 4; ++r)
            t[ty + 8 * r][tx] = W[(size_t)(e0 + ty + 8 * r) * EMBED + f0 + tx];
        __syncthreads();
        __half* Wt = g_Wt + (size_t)p * EMBED * EMBED;
        #pragma unroll
        for (int r = 0; r < 4; ++r)
            Wt[(size_t)(f0 + ty + 8 * r) * EMBED + e0 + tx] =
                __float2half_rn(t[tx][ty + 8 * r]);
    } else {
        const size_t base = (size_t)(b - WBLOCKS) * 1024 + tid;
        #pragma unroll
        for (int it = 0; it < 4; ++it) {
            const size_t idx = base + (size_t)it * 256;   // < 2,097,152
            float4 v = e[idx];
            __half2 lo = __floats2half2_rn(v.x, v.y);
            __half2 hi = __floats2half2_rn(v.z, v.w);
            reinterpret_cast<__half2*>(g_embh)[idx * 2 + 0] = lo;
            reinterpret_cast<__half2*>(g_embh)[idx * 2 + 1] = hi;
        }
    }
}

// ---------------- main kernel ----------------
__global__ void __launch_bounds__(THREADS, 2)
bilinear_kernel(const float* __restrict__ emb,
                const float* __restrict__ bias,
                float* __restrict__ out)
{
    extern __shared__ __half sm[];
    // layout: A buf0 | A buf1 | B buf0 | B buf1, each TILE_HALFS
    __half* Asm = sm;
    __half* Bsm = sm + 2 * TILE_HALFS;

    const int p   = blockIdx.z;
    const int bm0 = blockIdx.x * BM;
    const int bn0 = blockIdx.y * BN;

    // pair p -> (i, j) of triu_indices(16, k=1)
    int i = 0, rem = p;
    while (rem >= (NUM_FIELDS - 1) - i) { rem -= (NUM_FIELDS - 1) - i; ++i; }
    const int j = i + 1 + rem;

    const int tid  = threadIdx.x;
    const int lane = tid & 31;
    const int warp = tid >> 5;
    const int wm   = warp >> 2;   // 0..1  (64-row slab)
    const int wn   = warp & 3;    // 0..3  (32-col slab)
    const int g    = lane >> 2;   // 0..7
    const int t4   = lane & 3;    // 0..3

    const __half* Aglob = g_embh + (size_t)bm0 * (NUM_FIELDS * EMBED) + (size_t)i * EMBED;
    const __half* Bglob = g_Wt + (size_t)p * (EMBED * EMBED) + (size_t)bn0 * EMBED;

    float acc[4][4][4];
    #pragma unroll
    for (int mi = 0; mi < 4; ++mi)
        #pragma unroll
        for (int ni = 0; ni < 4; ++ni)
            #pragma unroll
            for (int r = 0; r < 4; ++r)
                acc[mi][ni][r] = 0.0f;

    // ---- async tile loaders: 128 rows x 64 halfs = 1024 x 16B each --------
    auto load_tiles = [&](int buf, int k0) {
        __half* Ad = Asm + buf * TILE_HALFS;
        __half* Bd = Bsm + buf * TILE_HALFS;
        #pragma unroll
        for (int it = 0; it < 4; ++it) {
            int idx = tid + it * THREADS;
            int m   = idx >> 3;          // 0..127
            int q   = idx & 7;           // 8-half chunk
            cp_async16(smem_u32(Ad + m * STRIDE + q * 8),
                       Aglob + (size_t)m * (NUM_FIELDS * EMBED) + k0 + q * 8);
        }
        #pragma unroll
        for (int it = 0; it < 4; ++it) {
            int idx = tid + it * THREADS;
            int n   = idx >> 3;          // 0..127
            int q   = idx & 7;
            cp_async16(smem_u32(Bd + n * STRIDE + q * 8),
                       Bglob + (size_t)n * EMBED + k0 + q * 8);
        }
    };

    const int NK = EMBED / BK;   // 4

    load_tiles(0, 0);
    cp_commit();

    for (int kt = 0; kt < NK; ++kt) {
        if (kt + 1 < NK) {
            load_tiles((kt + 1) & 1, (kt + 1) * BK);
            cp_commit();
            asm volatile("cp.async.wait_group 1;\n" ::: "memory");
        } else {
            asm volatile("cp.async.wait_group 0;\n" ::: "memory");
        }
        __syncthreads();

        const __half* Ab = Asm + (kt & 1) * TILE_HALFS;
        const __half* Bb = Bsm + (kt & 1) * TILE_HALFS;

        #pragma unroll
        for (int ks = 0; ks < BK / 16; ++ks) {
            const int kk = ks * 16;

            uint32_t afrag[4][4];
            #pragma unroll
            for (int mi = 0; mi < 4; ++mi) {
                const int rm = wm * 64 + mi * 16;
                afrag[mi][0] = *(const uint32_t*)(Ab + (rm + g    ) * STRIDE + kk + 2 * t4    );
                afrag[mi][1] = *(const uint32_t*)(Ab + (rm + g + 8) * STRIDE + kk + 2 * t4    );
                afrag[mi][2] = *(const uint32_t*)(Ab + (rm + g    ) * STRIDE + kk + 2 * t4 + 8);
                afrag[mi][3] = *(const uint32_t*)(Ab + (rm + g + 8) * STRIDE + kk + 2 * t4 + 8);
            }
            uint32_t bfrag[4][2];
            #pragma unroll
            for (int ni = 0; ni < 4; ++ni) {
                const int cn = wn * 32 + ni * 8 + g;
                bfrag[ni][0] = *(const uint32_t*)(Bb + cn * STRIDE + kk + 2 * t4    );
                bfrag[ni][1] = *(const uint32_t*)(Bb + cn * STRIDE + kk + 2 * t4 + 8);
            }
            #pragma unroll
            for (int mi = 0; mi < 4; ++mi)
                #pragma unroll
                for (int ni = 0; ni < 4; ++ni)
                    mma_f16(acc[mi][ni], afrag[mi], bfrag[ni]);
        }
        __syncthreads();
    }

    // ---- epilogue: out[b,p,f] = acc * emb[b,j,f] + bias[p,f] ---------------
    const float* biasP = bias + (size_t)p * EMBED;

    #pragma unroll
    for (int mi = 0; mi < 4; ++mi) {
        const int r0 = bm0 + wm * 64 + mi * 16 + g;
        #pragma unroll
        for (int ni = 0; ni < 4; ++ni) {
            const int c = bn0 + wn * 32 + ni * 8 + t4 * 2;
            const float2 bb = *(const float2*)(biasP + c);
            #pragma unroll
            for (int h = 0; h < 2; ++h) {
                const int row = r0 + h * 8;
                const float2 q = *(const float2*)(emb + (size_t)row * (NUM_FIELDS * EMBED)
                                                   + (size_t)j * EMBED + c);
                float2 v;
                v.x = acc[mi][ni][h * 2 + 0] * q.x + bb.x;
                v.y = acc[mi][ni][h * 2 + 1] * q.y + bb.y;
                *(float2*)(out + (size_t)row * (NUM_PAIRS * EMBED) + (size_t)p * EMBED + c) = v;
            }
        }
    }
}

extern "C" void kernel_launch(void* const* d_in, const int* in_sizes, int n_in,
                              void* d_out, int out_size) {
    const float* emb    = (const float*)d_in[0];
    const float* weight = (const float*)d_in[1];
    const float* bias   = (const float*)d_in[2];
    float* out          = (float*)d_out;

    cudaFuncSetAttribute(bilinear_kernel,
                         cudaFuncAttributeMaxDynamicSharedMemorySize, SMEM_BYTES);

    prep_all<<<WBLOCKS + EBLOCKS, 256>>>(weight, (const float4*)emb);

    dim3 grid(BATCH / BM, EMBED / BN, NUM_PAIRS);   // (16, 2, 120)
    bilinear_kernel<<<grid, THREADS, SMEM_BYTES>>>(emb, bias, out);
}

// round 11
// speedup vs baseline: 2.2706x; 1.0520x over previous
#include <cuda_runtime.h>
#include <cuda_fp16.h>
#include <cstdint>

// Problem constants
#define NUM_FIELDS 16
#define EMBED      256
#define BATCH      2048
#define NUM_PAIRS  120

// Tiling: CTA 128x128 with 4 warps (2x2), warp tile 64x64, BK=64, fp16 m16n8k16
#define BM 128
#define BN 128
#define BK 64
#define THREADS 128

#define STRIDE 72                 // halfs; fragment banks conflict-free (proven R9/R10)
#define TILE_HALFS (128 * STRIDE) // per operand per stage
#define SMEM_BYTES (4 * TILE_HALFS * 2)   // A0,A1,B0,B1 = 73728 B

// fp16 copies (allocation-free rule: __device__ globals)
__device__ __half g_Wt[(size_t)NUM_PAIRS * EMBED * EMBED];   // W^T: [p][f][e]
__device__ __half g_embh[(size_t)BATCH * NUM_FIELDS * EMBED];

__device__ __forceinline__ uint32_t smem_u32(const void* p) {
    return (uint32_t)__cvta_generic_to_shared(p);
}
__device__ __forceinline__ void cp_async16(uint32_t dst, const void* src) {
    asm volatile("cp.async.cg.shared.global [%0], [%1], 16;\n" :: "r"(dst), "l"(src));
}
__device__ __forceinline__ void cp_commit() {
    asm volatile("cp.async.commit_group;\n" ::: "memory");
}
__device__ __forceinline__ void mma_f16(float c[4], const uint32_t a[4], const uint32_t b[2]) {
    asm volatile(
        "mma.sync.aligned.m16n8k16.row.col.f32.f16.f16.f32 "
        "{%0,%1,%2,%3}, {%4,%5,%6,%7}, {%8,%9}, {%0,%1,%2,%3};\n"
        : "+f"(c[0]), "+f"(c[1]), "+f"(c[2]), "+f"(c[3])
        : "r"(a[0]), "r"(a[1]), "r"(a[2]), "r"(a[3]), "r"(b[0]), "r"(b[1]));
}

// ---------------- fused prep kernel ----------------
#define WBLOCKS 7680
#define EBLOCKS 2048

__global__ void prep_all(const float* __restrict__ w, const float4* __restrict__ e) {
    __shared__ float t[32][33];
    const int b = blockIdx.x;
    const int tid = threadIdx.x;

    if (b < WBLOCKS) {
        const int p   = b >> 6;
        const int til = b & 63;
        const int f0  = (til & 7) * 32;
        const int e0  = (til >> 3) * 32;
        const int tx = tid & 31, ty = tid >> 5;   // 32 x 8
        const float* W = w + (size_t)p * EMBED * EMBED;
        #pragma unroll
        for (int r = 0; r < 4; ++r)
            t[ty + 8 * r][tx] = W[(size_t)(e0 + ty + 8 * r) * EMBED + f0 + tx];
        __syncthreads();
        __half* Wt = g_Wt + (size_t)p * EMBED * EMBED;
        #pragma unroll
        for (int r = 0; r < 4; ++r)
            Wt[(size_t)(f0 + ty + 8 * r) * EMBED + e0 + tx] =
                __float2half_rn(t[tx][ty + 8 * r]);
    } else {
        const size_t base = (size_t)(b - WBLOCKS) * 1024 + tid;
        #pragma unroll
        for (int it = 0; it < 4; ++it) {
            const size_t idx = base + (size_t)it * 256;
            float4 v = e[idx];
            __half2 lo = __floats2half2_rn(v.x, v.y);
            __half2 hi = __floats2half2_rn(v.z, v.w);
            reinterpret_cast<__half2*>(g_embh)[idx * 2 + 0] = lo;
            reinterpret_cast<__half2*>(g_embh)[idx * 2 + 1] = hi;
        }
    }
}

// ---------------- main kernel ----------------
__global__ void __launch_bounds__(THREADS, 2)
bilinear_kernel(const float* __restrict__ emb,
                const float* __restrict__ bias,
                float* __restrict__ out)
{
    extern __shared__ __half sm[];
    __half* Asm = sm;
    __half* Bsm = sm + 2 * TILE_HALFS;

    const int p   = blockIdx.z;
    const int bm0 = blockIdx.x * BM;
    const int bn0 = blockIdx.y * BN;

    // pair p -> (i, j) of triu_indices(16, k=1)
    int i = 0, rem = p;
    while (rem >= (NUM_FIELDS - 1) - i) { rem -= (NUM_FIELDS - 1) - i; ++i; }
    const int j = i + 1 + rem;

    const int tid  = threadIdx.x;
    const int lane = tid & 31;
    const int warp = tid >> 5;    // 0..3
    const int wm   = warp >> 1;   // 0..1  (64-row slab)
    const int wn   = warp & 1;    // 0..1  (64-col slab)
    const int g    = lane >> 2;   // 0..7
    const int t4   = lane & 3;    // 0..3

    const __half* Aglob = g_embh + (size_t)bm0 * (NUM_FIELDS * EMBED) + (size_t)i * EMBED;
    const __half* Bglob = g_Wt + (size_t)p * (EMBED * EMBED) + (size_t)bn0 * EMBED;

    float acc[4][8][4];
    #pragma unroll
    for (int mi = 0; mi < 4; ++mi)
        #pragma unroll
        for (int ni = 0; ni < 8; ++ni)
            #pragma unroll
            for (int r = 0; r < 4; ++r)
                acc[mi][ni][r] = 0.0f;

    // ---- async tile loaders: 128 rows x 64 halfs = 1024 x 16B per operand --
    auto load_tiles = [&](int buf, int k0) {
        __half* Ad = Asm + buf * TILE_HALFS;
        __half* Bd = Bsm + buf * TILE_HALFS;
        #pragma unroll
        for (int it = 0; it < 8; ++it) {
            int idx = tid + it * THREADS;
            int m   = idx >> 3;          // 0..127
            int q   = idx & 7;           // 8-half chunk
            cp_async16(smem_u32(Ad + m * STRIDE + q * 8),
                       Aglob + (size_t)m * (NUM_FIELDS * EMBED) + k0 + q * 8);
        }
        #pragma unroll
        for (int it = 0; it < 8; ++it) {
            int idx = tid + it * THREADS;
            int n   = idx >> 3;
            int q   = idx & 7;
            cp_async16(smem_u32(Bd + n * STRIDE + q * 8),
                       Bglob + (size_t)n * EMBED + k0 + q * 8);
        }
    };

    const int NK = EMBED / BK;   // 4

    load_tiles(0, 0);
    cp_commit();

    for (int kt = 0; kt < NK; ++kt) {
        if (kt + 1 < NK) {
            load_tiles((kt + 1) & 1, (kt + 1) * BK);
            cp_commit();
            asm volatile("cp.async.wait_group 1;\n" ::: "memory");
        } else {
            asm volatile("cp.async.wait_group 0;\n" ::: "memory");
        }
        __syncthreads();

        const __half* Ab = Asm + (kt & 1) * TILE_HALFS;
        const __half* Bb = Bsm + (kt & 1) * TILE_HALFS;

        #pragma unroll
        for (int ks = 0; ks < BK / 16; ++ks) {
            const int kk = ks * 16;

            uint32_t afrag[4][4];
            #pragma unroll
            for (int mi = 0; mi < 4; ++mi) {
                const int rm = wm * 64 + mi * 16;
                afrag[mi][0] = *(const uint32_t*)(Ab + (rm + g    ) * STRIDE + kk + 2 * t4    );
                afrag[mi][1] = *(const uint32_t*)(Ab + (rm + g + 8) * STRIDE + kk + 2 * t4    );
                afrag[mi][2] = *(const uint32_t*)(Ab + (rm + g    ) * STRIDE + kk + 2 * t4 + 8);
                afrag[mi][3] = *(const uint32_t*)(Ab + (rm + g + 8) * STRIDE + kk + 2 * t4 + 8);
            }
            uint32_t bfrag[8][2];
            #pragma unroll
            for (int ni = 0; ni < 8; ++ni) {
                const int cn = wn * 64 + ni * 8 + g;
                bfrag[ni][0] = *(const uint32_t*)(Bb + cn * STRIDE + kk + 2 * t4    );
                bfrag[ni][1] = *(const uint32_t*)(Bb + cn * STRIDE + kk + 2 * t4 + 8);
            }
            #pragma unroll
            for (int mi = 0; mi < 4; ++mi)
                #pragma unroll
                for (int ni = 0; ni < 8; ++ni)
                    mma_f16(acc[mi][ni], afrag[mi], bfrag[ni]);
        }
        __syncthreads();
    }

    // ---- epilogue: out[b,p,f] = acc * emb[b,j,f] + bias[p,f] ---------------
    const float* biasP = bias + (size_t)p * EMBED;

    #pragma unroll
    for (int mi = 0; mi < 4; ++mi) {
        const int r0 = bm0 + wm * 64 + mi * 16 + g;
        #pragma unroll
        for (int ni = 0; ni < 8; ++ni) {
            const int c = bn0 + wn * 64 + ni * 8 + t4 * 2;
            const float2 bb = *(const float2*)(biasP + c);
            #pragma unroll
            for (int h = 0; h < 2; ++h) {
                const int row = r0 + h * 8;
                const float2 q = *(const float2*)(emb + (size_t)row * (NUM_FIELDS * EMBED)
                                                   + (size_t)j * EMBED + c);
                float2 v;
                v.x = acc[mi][ni][h * 2 + 0] * q.x + bb.x;
                v.y = acc[mi][ni][h * 2 + 1] * q.y + bb.y;
                *(float2*)(out + (size_t)row * (NUM_PAIRS * EMBED) + (size_t)p * EMBED + c) = v;
            }
        }
    }
}

extern "C" void kernel_launch(void* const* d_in, const int* in_sizes, int n_in,
                              void* d_out, int out_size) {
    const float* emb    = (const float*)d_in[0];
    const float* weight = (const float*)d_in[1];
    const float* bias   = (const float*)d_in[2];
    float* out          = (float*)d_out;

    cudaFuncSetAttribute(bilinear_kernel,
                         cudaFuncAttributeMaxDynamicSharedMemorySize, SMEM_BYTES);

    prep_all<<<WBLOCKS + EBLOCKS, 256>>>(weight, (const float4*)emb);

    dim3 grid(BATCH / BM, EMBED / BN, NUM_PAIRS);   // (16, 2, 120)
    bilinear_kernel<<<grid, THREADS, SMEM_BYTES>>>(emb, bias, out);
}